// round 14
// baseline (speedup 1.0000x reference)
#include <cuda_runtime.h>

// MedianPool2d 3x3, stride 1, reflect pad (1,1,1,1)
// float32 [16, 3, 512, 512] -> same shape.
//
// R14 = champion R7 body (40 regs, occ 64%, best bench 20.93us), with a
// placement-aware work mapping. Classic-launch CTA->SM placement on B300 is
// LUT[bid % 148]: bids congruent mod 148 run on the SAME SM, and L1 persists
// across CTA departures within a launch. We therefore assign each congruence
// class (= each SM) a CONTIGUOUS vertical strip of row-pair tiles:
//     bid = seq*148 + s   ->   tile t = s*84 + seq   (t < 12288)
// Consecutive tiles on one SM share 2 of their 4 input rows, so those rows
// are served from that SM's L1 (~39cy) instead of L2 (~250cy), attacking the
// per-warp L2-latency exposure that has pinned issue at ~68%.
// Body: packed f32x2 compare-exchange vertical stage (FMA pipe), scalar
// FMNMX sliding-window horizontal combine (ALU pipe), SHFL halos with
// lane-0/31 fixups, 32-bit offsets.

#define W 512
#define H 512

typedef unsigned long long u64;
typedef unsigned int u32;

__device__ __forceinline__ u64 pk(float x, float y) {
    u64 r; asm("mov.b64 %0, {%1, %2};" : "=l"(r) : "f"(x), "f"(y)); return r;
}
__device__ __forceinline__ float2 upk(u64 v) {
    float2 f; asm("mov.b64 {%0, %1}, %2;" : "=f"(f.x), "=f"(f.y) : "l"(v)); return f;
}

// packed compare-exchange on 2 fp32 lanes: lo=min, hi=max (FMA pipe)
__device__ __forceinline__ void cex2(u64 a, u64 b, u64& lo, u64& hi) {
    const u64 n1 = 0xBF800000BF800000ULL;
    const u64 hf = 0x3F0000003F000000ULL;
    const u64 nh = 0xBF000000BF000000ULL;
    u64 s, d, k, h;
    asm("add.rn.f32x2 %0, %1, %2;" : "=l"(s) : "l"(a), "l"(b));
    asm("fma.rn.f32x2 %0, %1, %2, %3;" : "=l"(d) : "l"(b), "l"(n1), "l"(a)); // a-b
    k = d & 0x7FFFFFFF7FFFFFFFULL;                                           // |a-b|
    asm("mul.rn.f32x2 %0, %1, %2;" : "=l"(h) : "l"(s), "l"(hf));             // 0.5(a+b)
    asm("fma.rn.f32x2 %0, %1, %2, %3;" : "=l"(lo) : "l"(k), "l"(nh), "l"(h));
    asm("fma.rn.f32x2 %0, %1, %2, %3;" : "=l"(hi) : "l"(k), "l"(hf), "l"(h));
}

__device__ __forceinline__ float med3(float a, float b, float c) {
    return fmaxf(fminf(a, b), fminf(fmaxf(a, b), c));
}

struct Row3 { u64 a, b, c; };   // packed columns (1,2) (3,4) (0,5)

__device__ __forceinline__ void emit_row(const Row3& pl, const Row3& ph,
                                         const Row3& t,
                                         float* __restrict__ dst) {
    float4 res;
    u64 loa, mia, hia, loc, mic, hic, tm;
    cex2(pl.a, t.a, loa, tm);
    cex2(ph.a, tm, mia, hia);
    cex2(pl.c, t.c, loc, tm);
    cex2(ph.c, tm, mic, hic);

    float2 la = upk(loa), lc = upk(loc);
    float2 ma = upk(mia), mc = upk(mic);
    float2 ha = upk(hia), hc = upk(hic);

    float sA  = fmaxf(la.x, la.y);
    float tA  = fminf(ha.x, ha.y);
    float q0A = fminf(ma.x, ma.y), q1A = fmaxf(ma.x, ma.y);

    u64 lob, mib, hib;
    cex2(pl.b, t.b, lob, tm);
    cex2(ph.b, tm, mib, hib);
    float2 lb = upk(lob), mb = upk(mib), hb = upk(hib);

    res.x = med3(fmaxf(lc.x, sA),
                 fmaxf(q0A, fminf(q1A, mc.x)),
                 fminf(hc.x, tA));
    res.y = med3(fmaxf(sA, lb.x),
                 fmaxf(q0A, fminf(q1A, mb.x)),
                 fminf(tA, hb.x));

    float sB  = fmaxf(lb.x, lb.y);
    float tB  = fminf(hb.x, hb.y);
    float q0B = fminf(mb.x, mb.y), q1B = fmaxf(mb.x, mb.y);

    res.z = med3(fmaxf(la.y, sB),
                 fmaxf(q0B, fminf(q1B, ma.y)),
                 fminf(ha.y, tB));
    res.w = med3(fmaxf(sB, lc.y),
                 fmaxf(q0B, fminf(q1B, mc.y)),
                 fminf(tB, hc.y));

    *reinterpret_cast<float4*>(dst) = res;
}

#define NSM   148u
#define SEQS  84u            // ceil(12288 / 148)
#define NTILE 12288u         // 256 row-pairs * 48 planes

__global__ __launch_bounds__(128, 12)
void median3x3_kernel(const float* __restrict__ x, float* __restrict__ out) {
    // placement-aware tile decode: bids congruent mod 148 (same SM) get
    // consecutive row-pair tiles (vertical strips) -> L1 row reuse.
    const u32 bid = blockIdx.x;
    const u32 s   = bid % NSM;
    const u32 seq = bid / NSM;
    const u32 t   = s * SEQS + seq;
    if (t >= NTILE) return;

    const u32 plane = t >> 8;             // 0..47
    const int h0    = (int)(t & 255u) << 1;

    const int tid   = threadIdx.x;        // 0..127
    const int lane  = tid & 31;
    const int w0    = tid << 2;

    const u32 base = plane * (u32)(H * W);

    // frame rows f0..f3 = input rows h0-1 .. h0+2 (reflected at edges)
    const u32 o1 = base + (u32)h0 * W;
    const u32 o2 = o1 + W;
    const u32 o0 = (h0 == 0)     ? o2 : o1 - W;   // reflect row -1 -> 1
    const u32 o3 = (h0 + 2 >= H) ? o1 : o2 + W;   // reflect row H -> H-2

    // 4 vector loads, back-to-back
    float4 q0 = *reinterpret_cast<const float4*>(x + o0 + w0);
    float4 q1 = *reinterpret_cast<const float4*>(x + o1 + w0);
    float4 q2 = *reinterpret_cast<const float4*>(x + o2 + w0);
    float4 q3 = *reinterpret_cast<const float4*>(x + o3 + w0);

    // halo exchange via shuffle; boundary lanes fix up with loads
    float l0 = __shfl_up_sync(0xffffffffu, q0.w, 1);
    float l1 = __shfl_up_sync(0xffffffffu, q1.w, 1);
    float l2 = __shfl_up_sync(0xffffffffu, q2.w, 1);
    float l3 = __shfl_up_sync(0xffffffffu, q3.w, 1);
    float e0 = __shfl_down_sync(0xffffffffu, q0.x, 1);
    float e1 = __shfl_down_sync(0xffffffffu, q1.x, 1);
    float e2 = __shfl_down_sync(0xffffffffu, q2.x, 1);
    float e3 = __shfl_down_sync(0xffffffffu, q3.x, 1);

    if (lane == 0) {
        if (w0 == 0) {
            l0 = q0.y; l1 = q1.y; l2 = q2.y; l3 = q3.y;     // reflect: wl = 1
        } else {
            l0 = x[o0 + w0 - 1]; l1 = x[o1 + w0 - 1];
            l2 = x[o2 + w0 - 1]; l3 = x[o3 + w0 - 1];
        }
    }
    if (lane == 31) {
        if (w0 + 4 == W) {
            e0 = q0.z; e1 = q1.z; e2 = q2.z; e3 = q3.z;     // reflect: wr = W-2
        } else {
            e0 = x[o0 + w0 + 4]; e1 = x[o1 + w0 + 4];
            e2 = x[o2 + w0 + 4]; e3 = x[o3 + w0 + 4];
        }
    }

    Row3 f0, f1, f2, f3;
    f0.a = pk(q0.x, q0.y); f0.b = pk(q0.z, q0.w); f0.c = pk(l0, e0);
    f1.a = pk(q1.x, q1.y); f1.b = pk(q1.z, q1.w); f1.c = pk(l1, e1);
    f2.a = pk(q2.x, q2.y); f2.b = pk(q2.z, q2.w); f2.c = pk(l2, e2);
    f3.a = pk(q3.x, q3.y); f3.b = pk(q3.z, q3.w); f3.c = pk(l3, e3);

    // pair sort rows f1,f2 (both die afterward)
    Row3 pl, ph;
    cex2(f1.a, f2.a, pl.a, ph.a);
    cex2(f1.b, f2.b, pl.b, ph.b);
    cex2(f1.c, f2.c, pl.c, ph.c);

    float* o = out + o1 + w0;
    emit_row(pl, ph, f0, o);        // output row h0
    emit_row(pl, ph, f3, o + W);    // output row h0+1
}

extern "C" void kernel_launch(void* const* d_in, const int* in_sizes, int n_in,
                              void* d_out, int out_size) {
    const float* x = (const float*)d_in[0];
    float* out = (float*)d_out;
    dim3 grid(NSM * SEQS);   // 12432 bids; 144 exit early
    dim3 block(128);
    median3x3_kernel<<<grid, block>>>(x, out);
}